// round 8
// baseline (speedup 1.0000x reference)
#include <cuda_runtime.h>
#include <cuda_bf16.h>
#include <cstdint>
#include <math.h>

// B=32, T=500, E=1024, D=1024, EMB=256, O=5000, olen=100, A=512
#define NBLK 148
#define NTHR 256

// ---------------- scratch layout (floats) ----------------
#define OFF_EYS   ((size_t)0)          // (100,32,256)
#define OFF_SB    ((size_t)819200)     // (100,32,2048)
#define OFF_SBX   ((size_t)7372800)    // (100,32,1024)
#define OFF_ENC   ((size_t)10649600)   // (32,500,512)
#define OFF_HSUM  ((size_t)18841600)
#define OFF_H     ((size_t)18874368)
#define OFF_H1    ((size_t)18907136)
#define OFF_C     ((size_t)18939904)
#define OFF_EN    ((size_t)18972672)   // (32,500)
#define OFF_YM    ((size_t)18988672)   // (100,32)
#define OFF_L512  ((size_t)18991872)   // (32,512)
#define OFF_PA    ((size_t)19008256)   // 1.6M
#define OFF_PB    ((size_t)20608256)   // 1.2M
#define SZ_TOTAL  ((size_t)21808256)

__device__ float g_scratch[SZ_TOTAL];
__device__ unsigned g_bar_cnt;
__device__ volatile unsigned g_bar_gen;

// ---------------- grid barrier ----------------
__device__ __forceinline__ void gsync() {
    __syncthreads();
    if (threadIdx.x == 0) {
        __threadfence();
        unsigned gen = g_bar_gen;
        if (atomicAdd(&g_bar_cnt, 1u) == NBLK - 1) {
            g_bar_cnt = 0;
            __threadfence();
            g_bar_gen = gen + 1;
        } else {
            while (g_bar_gen == gen) { __nanosleep(32); }
            __threadfence();
        }
    }
    __syncthreads();
}

__device__ __forceinline__ float sigm(float x) { return 1.f / (1.f + expf(-x)); }

// ---------------- GEMM building blocks (32 rows x 256 cols tile) ----------------
// smem: sAT[32(kk)][32(row)], sW[32(kk)][256(col)]
__device__ __forceinline__ void load_A(const float* A, int ldA, int k0, float* sAT) {
    int tid = threadIdx.x;
    int r = tid & 31, q = tid >> 5;
    float4 v = *(const float4*)(A + (size_t)r * ldA + k0 + q * 4);
    sAT[(q*4+0)*32 + r] = v.x; sAT[(q*4+1)*32 + r] = v.y;
    sAT[(q*4+2)*32 + r] = v.z; sAT[(q*4+3)*32 + r] = v.w;
}

__device__ __forceinline__ void load_W(const float* W, int ldW, int k0,
                                       int colBase, int ncols, float* sW) {
    int tid = threadIdx.x;
    #pragma unroll
    for (int v8 = 0; v8 < 8; v8++) {
        int id = tid + v8 * 256;
        int kr = id >> 6;
        int c4 = (id & 63) << 2;
        const float* src = W + (size_t)(k0 + kr) * ldW + colBase + c4;
        float4 val;
        if (c4 + 4 <= ncols) {
            val = *(const float4*)src;
        } else {
            val.x = (c4 + 0 < ncols) ? src[0] : 0.f;
            val.y = (c4 + 1 < ncols) ? src[1] : 0.f;
            val.z = (c4 + 2 < ncols) ? src[2] : 0.f;
            val.w = (c4 + 3 < ncols) ? src[3] : 0.f;
        }
        *(float4*)(sW + kr * 256 + c4) = val;
    }
}

__device__ __forceinline__ void mma_chunk(float acc[8][4], const float* sAT, const float* sW) {
    int tid = threadIdx.x;
    int ct = tid & 63, rt = tid >> 6;
    #pragma unroll
    for (int kk = 0; kk < 32; kk++) {
        float4 a0 = *(const float4*)(sAT + kk * 32 + rt * 8);
        float4 a1 = *(const float4*)(sAT + kk * 32 + rt * 8 + 4);
        float4 w  = *(const float4*)(sW + kk * 256 + ct * 4);
        float av[8] = {a0.x, a0.y, a0.z, a0.w, a1.x, a1.y, a1.z, a1.w};
        float wv[4] = {w.x, w.y, w.z, w.w};
        #pragma unroll
        for (int i = 0; i < 8; i++)
            #pragma unroll
            for (int j = 0; j < 4; j++)
                acc[i][j] = fmaf(av[i], wv[j], acc[i][j]);
    }
}

__device__ __forceinline__ void store_tile(float acc[8][4], float* outBase,
                                           int Ntot, int ncols) {
    int tid = threadIdx.x;
    int ct = tid & 63, rt = tid >> 6;
    int c = ct * 4;
    #pragma unroll
    for (int i = 0; i < 8; i++) {
        float* dst = outBase + (size_t)(rt * 8 + i) * Ntot + c;
        if (c + 4 <= ncols) {
            *(float4*)dst = make_float4(acc[i][0], acc[i][1], acc[i][2], acc[i][3]);
        } else {
            #pragma unroll
            for (int q = 0; q < 4; q++)
                if (c + q < ncols) dst[q] = acc[i][q];
        }
    }
}

struct GPair { const float* A; int ldA; const float* W; int ldW; int K; };

__device__ void gemm_tile(const GPair* pr, int np, int ks, int KS,
                          int colBase, int ncols, float* outSlot, int Ntot,
                          float* sAT, float* sW) {
    float acc[8][4] = {};
    int gc = 0;
    for (int p = 0; p < np; p++) {
        for (int k0 = 0; k0 < pr[p].K; k0 += 32) {
            if ((gc++ % KS) != ks) continue;
            __syncthreads();
            load_A(pr[p].A, pr[p].ldA, k0, sAT);
            load_W(pr[p].W, pr[p].ldW, k0, colBase, ncols, sW);
            __syncthreads();
            mma_chunk(acc, sAT, sW);
        }
    }
    store_tile(acc, outSlot, Ntot, ncols);
}

// ---------------- megakernel ----------------
struct MKArgs {
    const float *hs, *U1, *Ux1, *U2, *b2, *Wc, *Ux2, *bUx2, *Wcx;
    const float *Ws, *bs, *Wy, *We, *Wlogit, *blogit, *Wdec, *Winit, *binit;
    const int* hlens;
    float* out;
};

__global__ void __launch_bounds__(NTHR, 1) k_mega(MKArgs a) {
    __shared__ float SM[9216];
    float* sAT = SM;
    float* sW  = SM + 1024;

    float* eys  = g_scratch + OFF_EYS;
    float* sb   = g_scratch + OFF_SB;
    float* sbx  = g_scratch + OFF_SBX;
    float* enc  = g_scratch + OFF_ENC;
    float* hsum = g_scratch + OFF_HSUM;
    float* h    = g_scratch + OFF_H;
    float* h1   = g_scratch + OFF_H1;
    float* cvec = g_scratch + OFF_C;
    float* en   = g_scratch + OFF_EN;
    float* ym   = g_scratch + OFF_YM;
    float* l512 = g_scratch + OFF_L512;
    float* pA   = g_scratch + OFF_PA;
    float* pB   = g_scratch + OFF_PB;

    const int tid = threadIdx.x;

    // ===== h0 = hsum @ Winit + binit =====
    for (int t = blockIdx.x; t < 128; t += NBLK) {
        int ct = t & 3, ks = t >> 2;
        GPair p = {hsum, 1024, a.Winit, 1024, 1024};
        gemm_tile(&p, 1, ks, 32, ct * 256, 256,
                  pA + (size_t)ks * 32768 + ct * 256, 1024, sAT, sW);
    }
    gsync();
    for (int idx = blockIdx.x * NTHR + tid; idx < 32768; idx += NBLK * NTHR) {
        float s = a.binit[idx & 1023];
        for (int sI = 0; sI < 32; sI++) s += pA[(size_t)sI * 32768 + idx];
        h[idx] = s;
    }
    gsync();

    for (int step = 0; step < 100; step++) {
        // ===== phase 1: gate1 = [h@U1 | h@Ux1], KS=12, 144 tiles =====
        for (int t = blockIdx.x; t < 144; t += NBLK) {
            int ct = t % 12, ks = t / 12;
            if (ct < 8) {
                GPair p = {h, 1024, a.U1, 2048, 1024};
                gemm_tile(&p, 1, ks, 12, ct * 256, 256,
                          pA + (size_t)ks * 98304 + ct * 256, 3072, sAT, sW);
            } else {
                GPair p = {h, 1024, a.Ux1, 1024, 1024};
                gemm_tile(&p, 1, ks, 12, (ct - 8) * 256, 256,
                          pA + (size_t)ks * 98304 + 2048 + (ct - 8) * 256, 3072, sAT, sW);
            }
        }
        gsync();

        // ===== phase 2: ew1 (fused) + dq GEMM chunk, 64 tiles =====
        for (int t = blockIdx.x; t < 64; t += NBLK) {
            int ct = t & 1, ks = t >> 1;     // chunk = ks
            __syncthreads();
            #pragma unroll
            for (int v = 0; v < 4; v++) {
                int idx = tid + v * 256;
                int r = idx >> 5, jj = idx & 31;
                int j = ks * 32 + jj;
                float prv = 0.f, uv = 0.f, hx = 0.f;
                #pragma unroll
                for (int s = 0; s < 12; s++) {
                    const float* P = pA + (size_t)s * 98304 + (size_t)r * 3072;
                    prv += P[j]; uv += P[1024 + j]; hx += P[2048 + j];
                }
                const float* x_ = sb + (size_t)step * 65536 + (size_t)r * 2048;
                prv = sigm(prv + x_[j]);
                uv  = sigm(uv + x_[1024 + j]);
                float ht = tanhf(hx * prv + sbx[(size_t)step * 32768 + r * 1024 + j]);
                float hold = h[r * 1024 + j];
                float m = ym[step * 32 + r];
                float h1v = m * (uv * hold + (1.f - uv) * ht) + (1.f - m) * hold;
                sAT[jj * 32 + r] = h1v;
                if (ct == 0) h1[r * 1024 + j] = h1v;
            }
            load_W(a.Wdec, 512, ks * 32, ct * 256, 256, sW);
            __syncthreads();
            float acc[8][4] = {};
            mma_chunk(acc, sAT, sW);
            store_tile(acc, pB + (size_t)ks * 16384 + ct * 256, 512, 256);
        }
        gsync();

        // ===== phase 3: attention scores en[b,t] =====
        for (int t = blockIdx.x; t < 128; t += NBLK) {
            int b = t & 31, tch = t >> 5;
            __syncthreads();
            float* dqs = SM;
            for (int j = tid; j < 512; j += NTHR) {
                float s = 0.f;
                #pragma unroll 8
                for (int sI = 0; sI < 32; sI++)
                    s += pB[(size_t)sI * 16384 + b * 512 + j];
                dqs[j] = tanhf(s);
            }
            __syncthreads();
            int w = tid >> 5, l = tid & 31;
            int hl = a.hlens[b];
            for (int tt = tch * 125 + w; tt < tch * 125 + 125; tt += 8) {
                const float* row = enc + ((size_t)b * 500 + tt) * 512;
                float s = 0.f;
                #pragma unroll
                for (int q = 0; q < 16; q++)
                    s = fmaf(row[l + q * 32], dqs[l + q * 32], s);
                #pragma unroll
                for (int o = 16; o; o >>= 1) s += __shfl_xor_sync(0xffffffffu, s, o);
                if (l == 0) en[b * 500 + tt] = (tt < hl) ? s : -1e9f;
            }
        }
        gsync();

        // ===== phase 4: softmax(en) + context c =====
        for (int t = blockIdx.x; t < 128; t += NBLK) {
            int b = t & 31, ech = t >> 5;
            float* ws  = SM;
            float* red = SM + 512;
            __syncthreads();
            float v0 = (tid < 500) ? en[b * 500 + tid] : -1e30f;
            float v1 = (tid + 256 < 500) ? en[b * 500 + tid + 256] : -1e30f;
            float lm = fmaxf(v0, v1);
            #pragma unroll
            for (int o = 16; o; o >>= 1) lm = fmaxf(lm, __shfl_xor_sync(0xffffffffu, lm, o));
            if ((tid & 31) == 0) red[tid >> 5] = lm;
            __syncthreads();
            float gm = red[0];
            #pragma unroll
            for (int w = 1; w < 8; w++) gm = fmaxf(gm, red[w]);
            float e0 = (tid < 500) ? expf(v0 - gm) : 0.f;
            float e1 = (tid + 256 < 500) ? expf(v1 - gm) : 0.f;
            if (tid < 500) ws[tid] = e0;
            if (tid + 256 < 500) ws[tid + 256] = e1;
            float ls = e0 + e1;
            #pragma unroll
            for (int o = 16; o; o >>= 1) ls += __shfl_xor_sync(0xffffffffu, ls, o);
            __syncthreads();
            if ((tid & 31) == 0) red[tid >> 5] = ls;
            __syncthreads();
            float tot = 0.f;
            #pragma unroll
            for (int w = 0; w < 8; w++) tot += red[w];
            float inv = 1.f / tot;
            int e = ech * 256 + tid;
            const float* base = a.hs + (size_t)b * 512000 + e;
            float s0 = 0.f, s1 = 0.f, s2 = 0.f, s3 = 0.f;
            for (int t4 = 0; t4 < 500; t4 += 4) {
                s0 = fmaf(ws[t4],     base[(size_t)t4 * 1024], s0);
                s1 = fmaf(ws[t4 + 1], base[(size_t)(t4 + 1) * 1024], s1);
                s2 = fmaf(ws[t4 + 2], base[(size_t)(t4 + 2) * 1024], s2);
                s3 = fmaf(ws[t4 + 3], base[(size_t)(t4 + 3) * 1024], s3);
            }
            cvec[b * 1024 + e] = (s0 + s1 + s2 + s3) * inv;
        }
        gsync();

        // ===== phase 5: gate2 = [h1@U2+c@Wc | h1@Ux2 | c@Wcx], 144 tiles =====
        for (int t = blockIdx.x; t < 144; t += NBLK) {
            if (t < 96) {
                int ct = t % 8, ks = t / 8;       // KS=12, K=2048 (two pairs)
                GPair p2[2] = {{h1, 1024, a.U2, 2048, 1024},
                               {cvec, 1024, a.Wc, 2048, 1024}};
                gemm_tile(p2, 2, ks, 12, ct * 256, 256,
                          pA + (size_t)ks * 131072 + ct * 256, 4096, sAT, sW);
            } else if (t < 120) {
                int tt = t - 96, ct = tt % 4, ks = tt / 4;  // KS=6
                GPair p = {h1, 1024, a.Ux2, 1024, 1024};
                gemm_tile(&p, 1, ks, 6, ct * 256, 256,
                          pA + (size_t)ks * 131072 + 2048 + ct * 256, 4096, sAT, sW);
            } else {
                int tt = t - 120, ct = tt % 4, ks = tt / 4; // KS=6
                GPair p = {cvec, 1024, a.Wcx, 1024, 1024};
                gemm_tile(&p, 1, ks, 6, ct * 256, 256,
                          pA + (size_t)ks * 131072 + 3072 + ct * 256, 4096, sAT, sW);
            }
        }
        gsync();

        // ===== phase 6: ew2 (fused) + logit GEMM (h2@Ws + eys@Wy + c@We), 144 tiles =====
        for (int t = blockIdx.x; t < 144; t += NBLK) {
            int ct = t & 3, ks = t >> 2;         // ks 0..35; chunks {ks, ks+36} of 72
            float acc[8][4] = {};
            #pragma unroll
            for (int cc = 0; cc < 2; cc++) {
                int c = ks + cc * 36;
                __syncthreads();
                if (c < 32) {
                    // ew2 for cols [c*32, c*32+32) -> sAT; writer ct==0 stores h2
                    #pragma unroll
                    for (int v = 0; v < 4; v++) {
                        int idx = tid + v * 256;
                        int r = idx >> 5, jj = idx & 31;
                        int j = c * 32 + jj;
                        float prv = 0.f, uv = 0.f, hx = 0.f, cx = 0.f;
                        #pragma unroll
                        for (int s = 0; s < 12; s++) {
                            const float* P = pA + (size_t)s * 131072 + (size_t)r * 4096;
                            prv += P[j]; uv += P[1024 + j];
                        }
                        #pragma unroll
                        for (int s = 0; s < 6; s++) {
                            const float* P = pA + (size_t)s * 131072 + (size_t)r * 4096;
                            hx += P[2048 + j]; cx += P[3072 + j];
                        }
                        prv = sigm(prv + a.b2[j]);
                        uv  = sigm(uv + a.b2[1024 + j]);
                        float ht = tanhf((hx + a.bUx2[j]) * prv + cx);
                        float h1v = h1[r * 1024 + j];
                        float m = ym[step * 32 + r];
                        float h2v = m * (uv * h1v + (1.f - uv) * ht) + (1.f - m) * h1v;
                        sAT[jj * 32 + r] = h2v;
                        if (ct == 0) h[r * 1024 + j] = h2v;
                    }
                    load_W(a.Ws, 1024, c * 32, ct * 256, 256, sW);
                } else if (c < 40) {
                    load_A(eys + (size_t)step * 8192, 256, (c - 32) * 32, sAT);
                    load_W(a.Wy, 1024, (c - 32) * 32, ct * 256, 256, sW);
                } else {
                    load_A(cvec, 1024, (c - 40) * 32, sAT);
                    load_W(a.We, 1024, (c - 40) * 32, ct * 256, 256, sW);
                }
                __syncthreads();
                mma_chunk(acc, sAT, sW);
            }
            store_tile(acc, pB + (size_t)ks * 32768 + ct * 256, 1024, 256);
        }
        gsync();

        // ===== phase 7: pool (sum 36 slots + bias, pairwise max) -> l512 =====
        for (int idx = blockIdx.x * NTHR + tid; idx < 16384; idx += NBLK * NTHR) {
            int r = idx >> 9, p2 = idx & 511;
            float v0 = a.bs[2 * p2], v1 = a.bs[2 * p2 + 1];
            #pragma unroll 4
            for (int s = 0; s < 36; s++) {
                const float* P = pB + (size_t)s * 32768 + (size_t)r * 1024;
                v0 += P[2 * p2]; v1 += P[2 * p2 + 1];
            }
            l512[idx] = fmaxf(v0, v1);
        }
        gsync();

        // ===== phase 8: logits5000 = l512 @ Wlogit, 140 tiles =====
        for (int t = blockIdx.x; t < 140; t += NBLK) {
            int ct = t % 20, ks = t / 20;        // KS=7
            int ncols = 5000 - ct * 256; if (ncols > 256) ncols = 256;
            GPair p = {l512, 512, a.Wlogit, 5000, 512};
            gemm_tile(&p, 1, ks, 7, ct * 256, ncols,
                      pA + (size_t)ks * 160000 + ct * 256, 5000, sAT, sW);
        }
        gsync();

        // ===== phase 9: output softmax over 5000, 32 tiles =====
        for (int t = blockIdx.x; t < 32; t += NBLK) {
            int b = t;
            float* buf = SM;
            float* red = SM + 5004;
            __syncthreads();
            float lm = -1e30f;
            for (int j = tid; j < 5000; j += NTHR) {
                float v = a.blogit[j];
                #pragma unroll
                for (int s = 0; s < 7; s++)
                    v += pA[(size_t)s * 160000 + (size_t)b * 5000 + j];
                buf[j] = v;
                lm = fmaxf(lm, v);
            }
            #pragma unroll
            for (int o = 16; o; o >>= 1) lm = fmaxf(lm, __shfl_xor_sync(0xffffffffu, lm, o));
            if ((tid & 31) == 0) red[tid >> 5] = lm;
            __syncthreads();
            float gm = red[0];
            #pragma unroll
            for (int w = 1; w < 8; w++) gm = fmaxf(gm, red[w]);
            float ls = 0.f;
            for (int j = tid; j < 5000; j += NTHR) {
                float e = expf(buf[j] - gm);
                buf[j] = e;
                ls += e;
            }
            #pragma unroll
            for (int o = 16; o; o >>= 1) ls += __shfl_xor_sync(0xffffffffu, ls, o);
            __syncthreads();
            if ((tid & 31) == 0) red[tid >> 5] = ls;
            __syncthreads();
            float tot = 0.f;
            #pragma unroll
            for (int w = 0; w < 8; w++) tot += red[w];
            float inv = 1.f / tot;
            float* o = a.out + (size_t)b * 500000 + (size_t)step * 5000;
            for (int j = tid; j < 5000; j += NTHR) o[j] = buf[j] * inv;
        }
        gsync();
    }
}

// ---------------- precompute kernels ----------------
__global__ void __launch_bounds__(256) k_tiled(const float* __restrict__ A,
                                               const float* __restrict__ W,
                                               const float* __restrict__ bias,
                                               float* __restrict__ C,
                                               int N, int K, int act) {
    __shared__ float sAT[16][68];
    __shared__ float sWt[16][64];
    int rowBase = blockIdx.y << 6;
    int colBase = blockIdx.x << 6;
    int tx = threadIdx.x & 15;
    int ty = threadIdx.x >> 4;
    float acc[4][4];
    #pragma unroll
    for (int i = 0; i < 4; i++)
        #pragma unroll
        for (int j = 0; j < 4; j++) acc[i][j] = 0.f;

    for (int k0 = 0; k0 < K; k0 += 16) {
        __syncthreads();
        {
            int r = threadIdx.x >> 2;
            int c4 = (threadIdx.x & 3) << 2;
            float4 v = *(const float4*)(A + (size_t)(rowBase + r) * K + k0 + c4);
            sAT[c4+0][r] = v.x; sAT[c4+1][r] = v.y;
            sAT[c4+2][r] = v.z; sAT[c4+3][r] = v.w;
            int kr = threadIdx.x >> 4;
            int wc = (threadIdx.x & 15) << 2;
            *(float4*)&sWt[kr][wc] = *(const float4*)(W + (size_t)(k0 + kr) * N + colBase + wc);
        }
        __syncthreads();
        #pragma unroll
        for (int kk = 0; kk < 16; kk++) {
            float4 a4 = *(const float4*)&sAT[kk][ty << 2];
            float4 w4 = *(const float4*)&sWt[kk][tx << 2];
            float av[4] = {a4.x, a4.y, a4.z, a4.w};
            float wv[4] = {w4.x, w4.y, w4.z, w4.w};
            #pragma unroll
            for (int i = 0; i < 4; i++)
                #pragma unroll
                for (int j = 0; j < 4; j++)
                    acc[i][j] = fmaf(av[i], wv[j], acc[i][j]);
        }
    }
    #pragma unroll
    for (int i = 0; i < 4; i++) {
        int r = rowBase + (ty << 2) + i;
        #pragma unroll
        for (int j = 0; j < 4; j++) {
            int c = colBase + (tx << 2) + j;
            float v = acc[i][j];
            if (bias) v += bias[c];
            if (act == 1) v = tanhf(v);
            C[(size_t)r * N + c] = v;
        }
    }
}

__global__ void k_prep(const int* __restrict__ ys, float* __restrict__ ymask) {
    int b = threadIdx.x;
    if (b < 32) {
        int yl = 0;
        for (int j = 0; j < 99; j++) yl += (ys[b * 99 + j] != -1) ? 1 : 0;
        for (int i = 0; i < 100; i++)
            ymask[i * 32 + b] = (i < yl + 1) ? 1.f : 0.f;
    }
}

__global__ void k_eys(const int* __restrict__ ys, const float* __restrict__ embed,
                      float* __restrict__ eys) {
    int bx = blockIdx.x;          // i*32 + b
    int i = bx >> 5;
    int b = bx & 31;
    int tok = 4999;
    if (i > 0) { int v = ys[b * 99 + i - 1]; tok = (v < 0) ? 4999 : v; }
    int t = threadIdx.x;          // 64
    *(float4*)&eys[(size_t)bx * 256 + t * 4] =
        *(const float4*)&embed[(size_t)tok * 256 + t * 4];
}

__global__ void k_hsum(const float* __restrict__ hs, const int* __restrict__ hlens,
                       float* __restrict__ hsum) {
    int b = blockIdx.y;
    int e = blockIdx.x * 128 + threadIdx.x;
    const float* base = hs + (size_t)b * 512000 + e;
    float s0 = 0.f, s1 = 0.f, s2 = 0.f, s3 = 0.f;
    for (int t = 0; t < 500; t += 4) {
        s0 += base[(size_t)t * 1024];
        s1 += base[(size_t)(t + 1) * 1024];
        s2 += base[(size_t)(t + 2) * 1024];
        s3 += base[(size_t)(t + 3) * 1024];
    }
    hsum[b * 1024 + e] = (s0 + s1 + s2 + s3) / (float)hlens[b];
}

// ---------------- host launcher ----------------
extern "C" void kernel_launch(void* const* d_in, const int* in_sizes, int n_in,
                              void* d_out, int out_size) {
    const float* hs     = (const float*)d_in[0];
    const int*   hlens  = (const int*)  d_in[1];
    const int*   ys     = (const int*)  d_in[2];
    const float* embed  = (const float*)d_in[3];
    const float* W1_W   = (const float*)d_in[4];
    const float* b1_W   = (const float*)d_in[5];
    const float* W1_Wx  = (const float*)d_in[6];
    const float* b1_Wx  = (const float*)d_in[7];
    const float* U1     = (const float*)d_in[8];
    const float* Ux1    = (const float*)d_in[9];
    const float* U2     = (const float*)d_in[10];
    const float* b2     = (const float*)d_in[11];
    const float* Wc     = (const float*)d_in[12];
    const float* Ux2    = (const float*)d_in[13];
    const float* bUx2   = (const float*)d_in[14];
    const float* Wcx    = (const float*)d_in[15];
    const float* Winit  = (const float*)d_in[16];
    const float* binit  = (const float*)d_in[17];
    const float* Ws     = (const float*)d_in[18];
    const float* bs     = (const float*)d_in[19];
    const float* Wy     = (const float*)d_in[20];
    const float* We     = (const float*)d_in[21];
    const float* Wlogit = (const float*)d_in[22];
    const float* blogit = (const float*)d_in[23];
    const float* Wenc   = (const float*)d_in[24];
    const float* Wdec   = (const float*)d_in[25];

    float* scratch = nullptr;
    cudaGetSymbolAddress((void**)&scratch, g_scratch);
    float* eys = scratch + OFF_EYS;
    float* sb  = scratch + OFF_SB;
    float* sbx = scratch + OFF_SBX;
    float* enc = scratch + OFF_ENC;
    float* hsm = scratch + OFF_HSUM;
    float* ym  = scratch + OFF_YM;

    // precompute (6 nodes)
    k_prep<<<1, 32>>>(ys, ym);
    k_eys<<<3200, 64>>>(ys, embed, eys);
    k_hsum<<<dim3(8, 32), 128>>>(hs, hlens, hsm);
    k_tiled<<<dim3(32, 50), 256>>>(eys, W1_W, b1_W, sb, 2048, 256, 0);
    k_tiled<<<dim3(16, 50), 256>>>(eys, W1_Wx, b1_Wx, sbx, 1024, 256, 0);
    k_tiled<<<dim3(8, 250), 256>>>(hs, Wenc, nullptr, enc, 512, 1024, 1);

    // megakernel (1 node)
    MKArgs a;
    a.hs = hs; a.U1 = U1; a.Ux1 = Ux1; a.U2 = U2; a.b2 = b2; a.Wc = Wc;
    a.Ux2 = Ux2; a.bUx2 = bUx2; a.Wcx = Wcx; a.Ws = Ws; a.bs = bs;
    a.Wy = Wy; a.We = We; a.Wlogit = Wlogit; a.blogit = blogit;
    a.Wdec = Wdec; a.Winit = Winit; a.binit = binit; a.hlens = hlens;
    a.out = (float*)d_out;
    k_mega<<<NBLK, NTHR>>>(a);
}

// round 9
// speedup vs baseline: 2.1022x; 2.1022x over previous
#include <cuda_runtime.h>
#include <cuda_bf16.h>
#include <cstdint>
#include <math.h>

// B=32, T=500, E=1024, D=1024, EMB=256, O=5000, olen=100, A=512
#define NBLK 148
#define NTHR 256

// ---------------- scratch layout (floats) ----------------
#define OFF_EYS   ((size_t)0)          // (100,32,256)
#define OFF_SB    ((size_t)819200)     // (100,32,2048)
#define OFF_SBX   ((size_t)7372800)    // (100,32,1024)
#define OFF_ENC   ((size_t)10649600)   // (32,500,512)
#define OFF_HSUM  ((size_t)18841600)
#define OFF_H     ((size_t)18874368)
#define OFF_H1    ((size_t)18907136)
#define OFF_C     ((size_t)18939904)
#define OFF_EN    ((size_t)18972672)   // (32,500)
#define OFF_YM    ((size_t)18988672)   // (100,32)
#define OFF_L512  ((size_t)18991872)   // (32,512)
#define OFF_PA    ((size_t)19008256)   // 1.6M
#define OFF_PB    ((size_t)20608256)   // 1.2M
#define OFF_MS    ((size_t)21808256)   // (32,4,2) max/sum
#define SZ_TOTAL  ((size_t)21808512)

__device__ float g_scratch[SZ_TOTAL];
__device__ unsigned g_bar_cnt;

__global__ void k_rst() { g_bar_cnt = 0; }

// ---------------- grid barrier: REDG arrive + acquire poll ----------------
__device__ __forceinline__ void gsync(unsigned& gen) {
    gen += NBLK;
    __syncthreads();
    if (threadIdx.x == 0) {
        asm volatile("red.release.gpu.global.add.u32 [%0], 1;"
                     :: "l"(&g_bar_cnt) : "memory");
        unsigned v;
        while (true) {
            asm volatile("ld.acquire.gpu.global.u32 %0, [%1];"
                         : "=r"(v) : "l"(&g_bar_cnt) : "memory");
            if ((int)(v - gen) >= 0) break;
            __nanosleep(64);
        }
    }
    __syncthreads();
}

__device__ __forceinline__ float sigm(float x) { return 1.f / (1.f + expf(-x)); }

// ---------------- GEMM building blocks (32 rows x 256 cols tile) ----------------
// abuf: [32(kk)][32(row)], wbuf: [32(kk)][256(col)]
__device__ __forceinline__ void load_A(const float* A, int ldA, int k0, float* sAT) {
    int tid = threadIdx.x;
    int r = tid & 31, q = tid >> 5;
    float4 v = *(const float4*)(A + (size_t)r * ldA + k0 + q * 4);
    sAT[(q*4+0)*32 + r] = v.x; sAT[(q*4+1)*32 + r] = v.y;
    sAT[(q*4+2)*32 + r] = v.z; sAT[(q*4+3)*32 + r] = v.w;
}

__device__ __forceinline__ void load_W_sync(const float* W, int ldW, int k0,
                                            int colBase, int ncols, float* sW) {
    int tid = threadIdx.x;
    #pragma unroll
    for (int v8 = 0; v8 < 8; v8++) {
        int id = tid + v8 * 256;
        int kr = id >> 6;
        int c4 = (id & 63) << 2;
        const float* src = W + (size_t)(k0 + kr) * ldW + colBase + c4;
        float4 val;
        if (c4 + 4 <= ncols) {
            val = *(const float4*)src;
        } else {
            val.x = (c4 + 0 < ncols) ? src[0] : 0.f;
            val.y = (c4 + 1 < ncols) ? src[1] : 0.f;
            val.z = (c4 + 2 < ncols) ? src[2] : 0.f;
            val.w = (c4 + 3 < ncols) ? src[3] : 0.f;
        }
        *(float4*)(sW + kr * 256 + c4) = val;
    }
}

__device__ __forceinline__ void load_W_async(const float* W, int ldW, int k0,
                                             int colBase, int ncols, float* sWdst) {
    unsigned sbase = (unsigned)__cvta_generic_to_shared(sWdst);
    int tid = threadIdx.x;
    #pragma unroll
    for (int v8 = 0; v8 < 8; v8++) {
        int id = tid + v8 * 256;
        int kr = id >> 6;
        int c4 = (id & 63) << 2;
        int rem = ncols - c4;
        int sz = rem >= 4 ? 16 : (rem > 0 ? rem * 4 : 0);
        int cc = (sz > 0) ? c4 : 0;
        const float* src = W + (size_t)(k0 + kr) * ldW + colBase + cc;
        unsigned d = sbase + (unsigned)((kr * 256 + c4) * 4);
        asm volatile("cp.async.cg.shared.global [%0], [%1], 16, %2;"
                     :: "r"(d), "l"(src), "r"(sz));
    }
}

// packed f32x2 MMA: acc[i][j] holds rows (rt*8+2i, rt*8+2i+1), col ct*4+j
__device__ __forceinline__ void mma_chunk(unsigned long long acc[4][4],
                                          const float* sAT, const float* sW) {
    int ct = threadIdx.x & 63, rt = threadIdx.x >> 6;
    #pragma unroll
    for (int kk = 0; kk < 32; kk++) {
        const unsigned long long* ap =
            (const unsigned long long*)(sAT + kk * 32 + rt * 8);
        unsigned long long a0 = ap[0], a1 = ap[1], a2 = ap[2], a3 = ap[3];
        float4 w = *(const float4*)(sW + kk * 256 + ct * 4);
        unsigned long long w0, w1, w2, w3;
        asm("mov.b64 %0, {%1,%1};" : "=l"(w0) : "f"(w.x));
        asm("mov.b64 %0, {%1,%1};" : "=l"(w1) : "f"(w.y));
        asm("mov.b64 %0, {%1,%1};" : "=l"(w2) : "f"(w.z));
        asm("mov.b64 %0, {%1,%1};" : "=l"(w3) : "f"(w.w));
        #define F2X(ac, av, wv) \
            asm("fma.rn.f32x2 %0, %1, %2, %0;" : "+l"(ac) : "l"(av), "l"(wv));
        F2X(acc[0][0], a0, w0) F2X(acc[0][1], a0, w1)
        F2X(acc[0][2], a0, w2) F2X(acc[0][3], a0, w3)
        F2X(acc[1][0], a1, w0) F2X(acc[1][1], a1, w1)
        F2X(acc[1][2], a1, w2) F2X(acc[1][3], a1, w3)
        F2X(acc[2][0], a2, w0) F2X(acc[2][1], a2, w1)
        F2X(acc[2][2], a2, w2) F2X(acc[2][3], a2, w3)
        F2X(acc[3][0], a3, w0) F2X(acc[3][1], a3, w1)
        F2X(acc[3][2], a3, w2) F2X(acc[3][3], a3, w3)
        #undef F2X
    }
}

__device__ __forceinline__ void store_tile(unsigned long long acc[4][4],
                                           float* outBase, int Ntot, int ncols) {
    int ct = threadIdx.x & 63, rt = threadIdx.x >> 6;
    int c = ct * 4;
    #pragma unroll
    for (int i = 0; i < 4; i++) {
        float lo[4], hi[4];
        #pragma unroll
        for (int j = 0; j < 4; j++)
            asm("mov.b64 {%0,%1}, %2;" : "=f"(lo[j]), "=f"(hi[j]) : "l"(acc[i][j]));
        float* d0 = outBase + (size_t)(rt * 8 + 2 * i) * Ntot + c;
        float* d1 = outBase + (size_t)(rt * 8 + 2 * i + 1) * Ntot + c;
        if (c + 4 <= ncols) {
            *(float4*)d0 = make_float4(lo[0], lo[1], lo[2], lo[3]);
            *(float4*)d1 = make_float4(hi[0], hi[1], hi[2], hi[3]);
        } else {
            #pragma unroll
            for (int q = 0; q < 4; q++)
                if (c + q < ncols) { d0[q] = lo[q]; d1[q] = hi[q]; }
        }
    }
}

struct GPair { const float* A; int ldA; const float* W; int ldW; int K; };

// double-buffered pipelined tile: cp.async W(i+1) overlaps compute(i)
__device__ void gemm_tile(const GPair* pr, int np, int ks, int KS,
                          int colBase, int ncols, float* outSlot, int Ntot,
                          float* abuf, float* wbuf) {
    unsigned long long acc[4][4] = {};
    int pidx[8], koff[8];
    int m = 0, gc = 0;
    for (int p = 0; p < np; p++)
        for (int k0 = 0; k0 < pr[p].K; k0 += 32)
            if ((gc++ % KS) == ks) { pidx[m] = p; koff[m] = k0; m++; }

    if (m > 0) {
        load_W_async(pr[pidx[0]].W, pr[pidx[0]].ldW, koff[0], colBase, ncols, wbuf);
        asm volatile("cp.async.commit_group;" ::: "memory");
        load_A(pr[pidx[0]].A, pr[pidx[0]].ldA, koff[0], abuf);
    }
    for (int i = 0; i < m; i++) {
        asm volatile("cp.async.wait_group 0;" ::: "memory");
        __syncthreads();
        if (i + 1 < m) {
            load_W_async(pr[pidx[i+1]].W, pr[pidx[i+1]].ldW, koff[i+1],
                         colBase, ncols, wbuf + ((i + 1) & 1) * 8192);
            asm volatile("cp.async.commit_group;" ::: "memory");
            load_A(pr[pidx[i+1]].A, pr[pidx[i+1]].ldA, koff[i+1],
                   abuf + ((i + 1) & 1) * 1024);
        }
        mma_chunk(acc, abuf + (i & 1) * 1024, wbuf + (i & 1) * 8192);
    }
    store_tile(acc, outSlot, Ntot, ncols);
}

// ---------------- megakernel ----------------
struct MKArgs {
    const float *hs, *U1, *Ux1, *U2, *b2, *Wc, *Ux2, *bUx2, *Wcx;
    const float *Ws, *bs, *Wy, *We, *Wlogit, *blogit, *Wdec, *Winit, *binit;
    const int* hlens;
    float* out;
};

__global__ void __launch_bounds__(NTHR, 1) k_mega(MKArgs a) {
    extern __shared__ float SM[];
    float* abuf = SM;          // 2048 floats (2 x 32x32)
    float* wbuf = SM + 2048;   // 16384 floats (2 x 32x256)

    float* eys  = g_scratch + OFF_EYS;
    float* sb   = g_scratch + OFF_SB;
    float* sbx  = g_scratch + OFF_SBX;
    float* enc  = g_scratch + OFF_ENC;
    float* hsum = g_scratch + OFF_HSUM;
    float* h    = g_scratch + OFF_H;
    float* h1   = g_scratch + OFF_H1;
    float* cvec = g_scratch + OFF_C;
    float* en   = g_scratch + OFF_EN;
    float* ym   = g_scratch + OFF_YM;
    float* l512 = g_scratch + OFF_L512;
    float* pA   = g_scratch + OFF_PA;
    float* pB   = g_scratch + OFF_PB;
    float* ms   = g_scratch + OFF_MS;

    const int tid = threadIdx.x;
    unsigned gen = 0;

    // ===== h0 = hsum @ Winit + binit =====
    for (int t = blockIdx.x; t < 128; t += NBLK) {
        int ct = t & 3, ks = t >> 2;
        GPair p = {hsum, 1024, a.Winit, 1024, 1024};
        gemm_tile(&p, 1, ks, 32, ct * 256, 256,
                  pA + (size_t)ks * 32768 + ct * 256, 1024, abuf, wbuf);
    }
    gsync(gen);
    for (int idx = blockIdx.x * NTHR + tid; idx < 32768; idx += NBLK * NTHR) {
        float s = a.binit[idx & 1023];
        for (int sI = 0; sI < 32; sI++) s += pA[(size_t)sI * 32768 + idx];
        h[idx] = s;
    }
    gsync(gen);

    for (int step = 0; step < 100; step++) {
        // ===== phase 1: gate1 = [h@U1 | h@Ux1], KS=12, 144 tiles =====
        for (int t = blockIdx.x; t < 144; t += NBLK) {
            int ct = t % 12, ks = t / 12;
            if (ct < 8) {
                GPair p = {h, 1024, a.U1, 2048, 1024};
                gemm_tile(&p, 1, ks, 12, ct * 256, 256,
                          pA + (size_t)ks * 98304 + ct * 256, 3072, abuf, wbuf);
            } else {
                GPair p = {h, 1024, a.Ux1, 1024, 1024};
                gemm_tile(&p, 1, ks, 12, (ct - 8) * 256, 256,
                          pA + (size_t)ks * 98304 + 2048 + (ct - 8) * 256, 3072, abuf, wbuf);
            }
        }
        gsync(gen);

        // ===== phase 2: ew1 (fused) + dq GEMM chunk, 64 tiles =====
        for (int t = blockIdx.x; t < 64; t += NBLK) {
            int ct = t & 1, ks = t >> 1;
            __syncthreads();
            #pragma unroll
            for (int v = 0; v < 4; v++) {
                int idx = tid + v * 256;
                int r = idx >> 5, jj = idx & 31;
                int j = ks * 32 + jj;
                float prv = 0.f, uv = 0.f, hx = 0.f;
                #pragma unroll
                for (int s = 0; s < 12; s++) {
                    const float* P = pA + (size_t)s * 98304 + (size_t)r * 3072;
                    prv += P[j]; uv += P[1024 + j]; hx += P[2048 + j];
                }
                const float* x_ = sb + (size_t)step * 65536 + (size_t)r * 2048;
                prv = sigm(prv + x_[j]);
                uv  = sigm(uv + x_[1024 + j]);
                float ht = tanhf(hx * prv + sbx[(size_t)step * 32768 + r * 1024 + j]);
                float hold = h[r * 1024 + j];
                float m = ym[step * 32 + r];
                float h1v = m * (uv * hold + (1.f - uv) * ht) + (1.f - m) * hold;
                abuf[jj * 32 + r] = h1v;
                if (ct == 0) h1[r * 1024 + j] = h1v;
            }
            load_W_sync(a.Wdec, 512, ks * 32, ct * 256, 256, wbuf);
            __syncthreads();
            unsigned long long acc[4][4] = {};
            mma_chunk(acc, abuf, wbuf);
            store_tile(acc, pB + (size_t)ks * 16384 + ct * 256, 512, 256);
        }
        gsync(gen);

        // ===== phase 3: attention scores en[b,t] =====
        for (int t = blockIdx.x; t < 128; t += NBLK) {
            int b = t & 31, tch = t >> 5;
            __syncthreads();
            float* dqs = SM;
            for (int j = tid; j < 512; j += NTHR) {
                float s = 0.f;
                #pragma unroll 8
                for (int sI = 0; sI < 32; sI++)
                    s += pB[(size_t)sI * 16384 + b * 512 + j];
                dqs[j] = tanhf(s);
            }
            __syncthreads();
            int w = tid >> 5, l = tid & 31;
            int hl = a.hlens[b];
            for (int tt = tch * 125 + w; tt < tch * 125 + 125; tt += 8) {
                const float* row = enc + ((size_t)b * 500 + tt) * 512;
                float s = 0.f;
                #pragma unroll
                for (int q = 0; q < 16; q++)
                    s = fmaf(row[l + q * 32], dqs[l + q * 32], s);
                #pragma unroll
                for (int o = 16; o; o >>= 1) s += __shfl_xor_sync(0xffffffffu, s, o);
                if (l == 0) en[b * 500 + tt] = (tt < hl) ? s : -1e9f;
            }
        }
        gsync(gen);

        // ===== phase 4: softmax(en) + context c =====
        for (int t = blockIdx.x; t < 128; t += NBLK) {
            int b = t & 31, ech = t >> 5;
            float* ws  = SM;
            float* red = SM + 1792;
            __syncthreads();
            float v0 = (tid < 500) ? en[b * 500 + tid] : -1e30f;
            float v1 = (tid + 256 < 500) ? en[b * 500 + tid + 256] : -1e30f;
            float lm = fmaxf(v0, v1);
            #pragma unroll
            for (int o = 16; o; o >>= 1) lm = fmaxf(lm, __shfl_xor_sync(0xffffffffu, lm, o));
            if ((tid & 31) == 0) red[tid >> 5] = lm;
            __syncthreads();
            float gm = red[0];
            #pragma unroll
            for (int w = 1; w < 8; w++) gm = fmaxf(gm, red[w]);
            float e0 = (tid < 500) ? expf(v0 - gm) : 0.f;
            float e1 = (tid + 256 < 500) ? expf(v1 - gm) : 0.f;
            if (tid < 500) ws[tid] = e0;
            if (tid + 256 < 500) ws[tid + 256] = e1;
            float ls = e0 + e1;
            #pragma unroll
            for (int o = 16; o; o >>= 1) ls += __shfl_xor_sync(0xffffffffu, ls, o);
            __syncthreads();
            if ((tid & 31) == 0) red[tid >> 5] = ls;
            __syncthreads();
            float tot = 0.f;
            #pragma unroll
            for (int w = 0; w < 8; w++) tot += red[w];
            float inv = 1.f / tot;
            int e = ech * 256 + tid;
            const float* base = a.hs + (size_t)b * 512000 + e;
            float s0 = 0.f, s1 = 0.f, s2 = 0.f, s3 = 0.f;
            for (int t4 = 0; t4 < 500; t4 += 4) {
                s0 = fmaf(ws[t4],     base[(size_t)t4 * 1024], s0);
                s1 = fmaf(ws[t4 + 1], base[(size_t)(t4 + 1) * 1024], s1);
                s2 = fmaf(ws[t4 + 2], base[(size_t)(t4 + 2) * 1024], s2);
                s3 = fmaf(ws[t4 + 3], base[(size_t)(t4 + 3) * 1024], s3);
            }
            cvec[b * 1024 + e] = (s0 + s1 + s2 + s3) * inv;
        }
        gsync(gen);

        // ===== phase 5: gate2 = [h1@U2+c@Wc | h1@Ux2 | c@Wcx], 144 tiles =====
        for (int t = blockIdx.x; t < 144; t += NBLK) {
            if (t < 96) {
                int ct = t % 8, ks = t / 8;       // KS=12, 64 chunks across 2 pairs
                GPair p2[2] = {{h1, 1024, a.U2, 2048, 1024},
                               {cvec, 1024, a.Wc, 2048, 1024}};
                gemm_tile(p2, 2, ks, 12, ct * 256, 256,
                          pA + (size_t)ks * 131072 + ct * 256, 4096, abuf, wbuf);
            } else if (t < 120) {
                int tt = t - 96, ct = tt % 4, ks = tt / 4;  // KS=6
                GPair p = {h1, 1024, a.Ux2, 1024, 1024};
                gemm_tile(&p, 1, ks, 6, ct * 256, 256,
                          pA + (size_t)ks * 131072 + 2048 + ct * 256, 4096, abuf, wbuf);
            } else {
                int tt = t - 120, ct = tt % 4, ks = tt / 4; // KS=6
                GPair p = {cvec, 1024, a.Wcx, 1024, 1024};
                gemm_tile(&p, 1, ks, 6, ct * 256, 256,
                          pA + (size_t)ks * 131072 + 3072 + ct * 256, 4096, abuf, wbuf);
            }
        }
        gsync(gen);

        // ===== phase 6: ew2 (fused) + logit GEMM, 144 tiles =====
        for (int t = blockIdx.x; t < 144; t += NBLK) {
            int ct = t & 3, ks = t >> 2;         // ks 0..35; chunks {ks, ks+36}
            unsigned long long acc[4][4] = {};
            #pragma unroll
            for (int cc = 0; cc < 2; cc++) {
                int c = ks + cc * 36;
                __syncthreads();
                if (c < 32) {
                    #pragma unroll
                    for (int v = 0; v < 4; v++) {
                        int idx = tid + v * 256;
                        int r = idx >> 5, jj = idx & 31;
                        int j = c * 32 + jj;
                        float prv = 0.f, uv = 0.f, hx = 0.f, cx = 0.f;
                        #pragma unroll
                        for (int s = 0; s < 12; s++) {
                            const float* P = pA + (size_t)s * 131072 + (size_t)r * 4096;
                            prv += P[j]; uv += P[1024 + j];
                        }
                        #pragma unroll
                        for (int s = 0; s < 6; s++) {
                            const float* P = pA + (size_t)s * 131072 + (size_t)r * 4096;
                            hx += P[2048 + j]; cx += P[3072 + j];
                        }
                        prv = sigm(prv + a.b2[j]);
                        uv  = sigm(uv + a.b2[1024 + j]);
                        float ht = tanhf((hx + a.bUx2[j]) * prv + cx);
                        float h1v = h1[r * 1024 + j];
                        float m = ym[step * 32 + r];
                        float h2v = m * (uv * h1v + (1.f - uv) * ht) + (1.f - m) * h1v;
                        abuf[jj * 32 + r] = h2v;
                        if (ct == 0) h[r * 1024 + j] = h2v;
                    }
                    load_W_sync(a.Ws, 1024, c * 32, ct * 256, 256, wbuf);
                } else if (c < 40) {
                    load_A(eys + (size_t)step * 8192, 256, (c - 32) * 32, abuf);
                    load_W_sync(a.Wy, 1024, (c - 32) * 32, ct * 256, 256, wbuf);
                } else {
                    load_A(cvec, 1024, (c - 40) * 32, abuf);
                    load_W_sync(a.We, 1024, (c - 40) * 32, ct * 256, 256, wbuf);
                }
                __syncthreads();
                mma_chunk(acc, abuf, wbuf);
            }
            store_tile(acc, pB + (size_t)ks * 32768 + ct * 256, 1024, 256);
        }
        gsync(gen);

        // ===== phase 7: pool (sum 36 slots + bias, pairwise max) -> l512 =====
        for (int idx = blockIdx.x * NTHR + tid; idx < 16384; idx += NBLK * NTHR) {
            int r = idx >> 9, p2 = idx & 511;
            float v0 = a.bs[2 * p2], v1 = a.bs[2 * p2 + 1];
            #pragma unroll 4
            for (int s = 0; s < 36; s++) {
                const float* P = pB + (size_t)s * 32768 + (size_t)r * 1024;
                v0 += P[2 * p2]; v1 += P[2 * p2 + 1];
            }
            l512[idx] = fmaxf(v0, v1);
        }
        gsync(gen);

        // ===== phase 8: logits5000 = l512 @ Wlogit, 140 tiles =====
        for (int t = blockIdx.x; t < 140; t += NBLK) {
            int ct = t % 20, ks = t / 20;        // KS=7
            int ncols = 5000 - ct * 256; if (ncols > 256) ncols = 256;
            GPair p = {l512, 512, a.Wlogit, 5000, 512};
            gemm_tile(&p, 1, ks, 7, ct * 256, ncols,
                      pA + (size_t)ks * 160000 + ct * 256, 5000, abuf, wbuf);
        }
        gsync(gen);

        // ===== phase 9a: reduce partials + local max + exp, 128 tiles =====
        for (int t = blockIdx.x; t < 128; t += NBLK) {
            int b = t & 31, q = t >> 5;          // cols [q*1250, q*1250+1250)
            float* buf = SM;
            float* red = SM + 1792;
            __syncthreads();
            float lm = -1e30f;
            for (int j0 = tid; j0 < 1250; j0 += NTHR) {
                int j = q * 1250 + j0;
                float v = a.blogit[j];
                #pragma unroll
                for (int s = 0; s < 7; s++)
                    v += pA[(size_t)s * 160000 + (size_t)b * 5000 + j];
                buf[j0] = v;
                lm = fmaxf(lm, v);
            }
            #pragma unroll
            for (int o = 16; o; o >>= 1) lm = fmaxf(lm, __shfl_xor_sync(0xffffffffu, lm, o));
            if ((tid & 31) == 0) red[tid >> 5] = lm;
            __syncthreads();
            float gml = red[0];
            #pragma unroll
            for (int w = 1; w < 8; w++) gml = fmaxf(gml, red[w]);
            float ls = 0.f;
            for (int j0 = tid; j0 < 1250; j0 += NTHR) {
                float e = expf(buf[j0] - gml);
                pB[(size_t)b * 5000 + q * 1250 + j0] = e;
                ls += e;
            }
            #pragma unroll
            for (int o = 16; o; o >>= 1) ls += __shfl_xor_sync(0xffffffffu, ls, o);
            __syncthreads();
            if ((tid & 31) == 0) red[tid >> 5] = ls;
            __syncthreads();
            if (tid == 0) {
                float tot = 0.f;
                #pragma unroll
                for (int w = 0; w < 8; w++) tot += red[w];
                ms[(b * 4 + q) * 2]     = gml;
                ms[(b * 4 + q) * 2 + 1] = tot;
            }
        }
        gsync(gen);

        // ===== phase 9b: combine + write output =====
        for (int t = blockIdx.x; t < 128; t += NBLK) {
            int b = t & 31, q = t >> 5;
            float m0 = ms[(b*4+0)*2], m1 = ms[(b*4+1)*2];
            float m2 = ms[(b*4+2)*2], m3 = ms[(b*4+3)*2];
            float gm = fmaxf(fmaxf(m0, m1), fmaxf(m2, m3));
            float gs = ms[(b*4+0)*2+1] * expf(m0 - gm)
                     + ms[(b*4+1)*2+1] * expf(m1 - gm)
                     + ms[(b*4+2)*2+1] * expf(m2 - gm)
                     + ms[(b*4+3)*2+1] * expf(m3 - gm);
            float scale = expf(ms[(b*4+q)*2] - gm) / gs;
            float* o = a.out + (size_t)b * 500000 + (size_t)step * 5000 + q * 1250;
            const float* src = pB + (size_t)b * 5000 + q * 1250;
            for (int j0 = tid; j0 < 1250; j0 += NTHR) o[j0] = src[j0] * scale;
        }
        gsync(gen);
    }
}

// ---------------- precompute kernels ----------------
__global__ void __launch_bounds__(256) k_tiled(const float* __restrict__ A,
                                               const float* __restrict__ W,
                                               const float* __restrict__ bias,
                                               float* __restrict__ C,
                                               int N, int K, int act) {
    __shared__ float sAT[16][68];
    __shared__ float sWt[16][64];
    int rowBase = blockIdx.y << 6;
    int colBase = blockIdx.x << 6;
    int tx = threadIdx.x & 15;
    int ty = threadIdx.x >> 4;
    float acc[4][4];
    #pragma unroll
    for (int i = 0; i < 4; i++)
        #pragma unroll
        for (int j = 0; j < 4; j++) acc[i][j] = 0.f;

    for (int k0 = 0; k0 < K; k0 += 16) {
        __syncthreads();
        {
            int r = threadIdx.x >> 2;
            int c4 = (threadIdx.x & 3) << 2;
            float4 v = *(const float4*)(A + (size_t)(rowBase + r) * K + k0 + c4);
            sAT[c4+0][r] = v.x; sAT[c4+1][r] = v.y;
            sAT[c4+2][r] = v.z; sAT[c4+3][r] = v.w;
            int kr = threadIdx.x >> 4;
            int wc = (threadIdx.x & 15) << 2;
            *(float4*)&sWt[kr][wc] = *(const float4*)(W + (size_t)(k0 + kr) * N + colBase + wc);
        }
        __syncthreads();
        #pragma unroll
        for (int kk = 0; kk < 16; kk++) {
            float4 a4 = *(const float4*)&sAT[kk][ty << 2];
            float4 w4 = *(const float4*)&sWt[kk][tx << 2];
            float av[4] = {a4.x, a4.y, a4.z, a4.w};
            float wv[4] = {w4.x, w4.y, w4.z, w4.w};
            #pragma unroll
            for (int i = 0; i < 4; i++)
                #pragma unroll
                for (int j = 0; j < 4; j++)
                    acc[i][j] = fmaf(av[i], wv[j], acc[i][j]);
        }
    }
    #pragma unroll
    for (int i = 0; i < 4; i++) {
        int r = rowBase + (ty << 2) + i;
        #pragma unroll
        for (int j = 0; j < 4; j++) {
            int c = colBase + (tx << 2) + j;
            float v = acc[i][j];
            if (bias) v += bias[c];
            if (act == 1) v = tanhf(v);
            C[(size_t)r * N + c] = v;
        }
    }
}

__global__ void k_prep(const int* __restrict__ ys, float* __restrict__ ymask) {
    int b = threadIdx.x;
    if (b < 32) {
        int yl = 0;
        for (int j = 0; j < 99; j++) yl += (ys[b * 99 + j] != -1) ? 1 : 0;
        for (int i = 0; i < 100; i++)
            ymask[i * 32 + b] = (i < yl + 1) ? 1.f : 0.f;
    }
}

__global__ void k_eys(const int* __restrict__ ys, const float* __restrict__ embed,
                      float* __restrict__ eys) {
    int bx = blockIdx.x;          // i*32 + b
    int i = bx >> 5;
    int b = bx & 31;
    int tok = 4999;
    if (i > 0) { int v = ys[b * 99 + i - 1]; tok = (v < 0) ? 4999 : v; }
    int t = threadIdx.x;          // 64
    *(float4*)&eys[(size_t)bx * 256 + t * 4] =
        *(const float4*)&embed[(size_t)tok * 256 + t * 4];
}

__global__ void k_hsum(const float* __restrict__ hs, const int* __restrict__ hlens,
                       float* __restrict__ hsum) {
    int b = blockIdx.y;
    int e = blockIdx.x * 128 + threadIdx.x;
    const float* base = hs + (size_t)b * 512000 + e;
    float s0 = 0.f, s1 = 0.f, s2 = 0.f, s3 = 0.f;
    for (int t = 0; t < 500; t += 4) {
        s0 += base[(size_t)t * 1024];
        s1 += base[(size_t)(t + 1) * 1024];
        s2 += base[(size_t)(t + 2) * 1024];
        s3 += base[(size_t)(t + 3) * 1024];
    }
    hsum[b * 1024 + e] = (s0 + s1 + s2 + s3) / (float)hlens[b];
}

// ---------------- host launcher ----------------
extern "C" void kernel_launch(void* const* d_in, const int* in_sizes, int n_in,
                              void* d_out, int out_size) {
    const float* hs     = (const float*)d_in[0];
    const int*   hlens  = (const int*)  d_in[1];
    const int*   ys     = (const int*)  d_in[2];
    const float* embed  = (const float*)d_in[3];
    const float* W1_W   = (const float*)d_in[4];
    const float* b1_W   = (const float*)d_in[5];
    const float* W1_Wx  = (const float*)d_in[6];
    const float* b1_Wx  = (const float*)d_in[7];
    const float* U1     = (const float*)d_in[8];
    const float* Ux1    = (const float*)d_in[9];
    const float* U2     = (const float*)d_in[10];
    const float* b2     = (const float*)d_in[11];
    const float* Wc     = (const float*)d_in[12];
    const float* Ux2    = (const float*)d_in[13];
    const float* bUx2   = (const float*)d_in[14];
    const float* Wcx    = (const float*)d_in[15];
    const float* Winit  = (const float*)d_in[16];
    const float* binit  = (const float*)d_in[17];
    const float* Ws     = (const float*)d_in[18];
    const float* bs     = (const float*)d_in[19];
    const float* Wy     = (const float*)d_in[20];
    const float* We     = (const float*)d_in[21];
    const float* Wlogit = (const float*)d_in[22];
    const float* blogit = (const float*)d_in[23];
    const float* Wenc   = (const float*)d_in[24];
    const float* Wdec   = (const float*)d_in[25];

    float* scratch = nullptr;
    cudaGetSymbolAddress((void**)&scratch, g_scratch);
    float* eys = scratch + OFF_EYS;
    float* sb  = scratch + OFF_SB;
    float* sbx = scratch + OFF_SBX;
    float* enc = scratch + OFF_ENC;
    float* hsm = scratch + OFF_HSUM;
    float* ym  = scratch + OFF_YM;

    static bool attrSet = false;
    if (!attrSet) {
        cudaFuncSetAttribute(k_mega, cudaFuncAttributeMaxDynamicSharedMemorySize,
                             73728);
        attrSet = true;
    }

    // precompute
    k_prep<<<1, 32>>>(ys, ym);
    k_eys<<<3200, 64>>>(ys, embed, eys);
    k_hsum<<<dim3(8, 32), 128>>>(hs, hlens, hsm);
    k_tiled<<<dim3(32, 50), 256>>>(eys, W1_W, b1_W, sb, 2048, 256, 0);
    k_tiled<<<dim3(16, 50), 256>>>(eys, W1_Wx, b1_Wx, sbx, 1024, 256, 0);
    k_tiled<<<dim3(8, 250), 256>>>(hs, Wenc, nullptr, enc, 512, 1024, 1);
    k_rst<<<1, 1>>>();

    // megakernel
    MKArgs a;
    a.hs = hs; a.U1 = U1; a.Ux1 = Ux1; a.U2 = U2; a.b2 = b2; a.Wc = Wc;
    a.Ux2 = Ux2; a.bUx2 = bUx2; a.Wcx = Wcx; a.Ws = Ws; a.bs = bs;
    a.Wy = Wy; a.We = We; a.Wlogit = Wlogit; a.blogit = blogit;
    a.Wdec = Wdec; a.Winit = Winit; a.binit = binit; a.hlens = hlens;
    a.out = (float*)d_out;
    k_mega<<<NBLK, NTHR, 73728>>>(a);
}